// round 16
// baseline (speedup 1.0000x reference)
#include <cuda_runtime.h>
#include <cstdint>

// ---------------- problem constants ----------------
#define DDIM    64
#define MTOT    1024
#define NTRAIN  4096
#define TM      128                // CTA M tile
#define TN      128                // CTA N tile
#define NSPLIT  (NTRAIN / TN)      // 32
#define MT      (MTOT / TM)        // 8
#define CC      901.6844f          // log2(e)/var, var = 0.0016
#define HS      450.8422f          // 0.5*CC
#define INVCC   (1.0f / 901.6844f)

// deterministic cross-block scratch + self-resetting counters
__device__ float g_scratch[NSPLIT * MTOT];
__device__ int   g_cnt[MT];

// ---- dynamic smem layout (bytes) ----
#define OFF_A     0                 // bf16 A tile, SW128: 128*128B
#define OFF_B     16384             // bf16 B tile, SW128: 128*128B
#define OFF_BRAW  32768             // raw fp32 B tile: 128*256B (cp.async dest)
#define OFF_HSA   65536             // 128 f32
#define OFF_HSB   66048             // 128 f32
#define OFF_RED   66560             // 2*128 f32
#define SMEM_BYTES 67584

__device__ __forceinline__ uint32_t smem_u32(const void* p) {
    return (uint32_t)__cvta_generic_to_shared(p);
}
__device__ __forceinline__ uint32_t bf16x2_pack(float lo, float hi) {
    uint32_t r;
    asm("cvt.rn.bf16x2.f32 %0, %1, %2;" : "=r"(r) : "f"(hi), "f"(lo));
    return r;
}
__device__ __forceinline__ float ex2f(float x) {
    float y; asm("ex2.approx.f32 %0, %1;" : "=f"(y) : "f"(x)); return y;
}
__device__ __forceinline__ uint32_t sw128(uint32_t o) {
    return o ^ ((o >> 3) & 0x70);
}
__device__ __forceinline__ void ldsm4(uint32_t r[4], uint32_t addr) {
    asm volatile("ldmatrix.sync.aligned.m8n8.x4.shared.b16 {%0,%1,%2,%3}, [%4];"
                 : "=r"(r[0]), "=r"(r[1]), "=r"(r[2]), "=r"(r[3]) : "r"(addr));
}
__device__ __forceinline__ void mma16816(float d[4], const uint32_t a[4],
                                         uint32_t b0, uint32_t b1) {
    asm volatile("mma.sync.aligned.m16n8k16.row.col.f32.bf16.bf16.f32 "
                 "{%0,%1,%2,%3}, {%4,%5,%6,%7}, {%8,%9}, {%0,%1,%2,%3};"
                 : "+f"(d[0]), "+f"(d[1]), "+f"(d[2]), "+f"(d[3])
                 : "r"(a[0]), "r"(a[1]), "r"(a[2]), "r"(a[3]),
                   "r"(b0), "r"(b1));
}
__device__ __forceinline__ void cp_async16(uint32_t daddr, const void* gptr) {
    asm volatile("cp.async.ca.shared.global [%0], [%1], 16;"
                 :: "r"(daddr), "l"(gptr) : "memory");
}

__global__ __launch_bounds__(256, 2)
void kde_mma(const float* __restrict__ test_x,
             const float* __restrict__ train_x,
             float* __restrict__ out)
{
    extern __shared__ char sm[];
    float* hsa = (float*)(sm + OFF_HSA);
    float* hsb = (float*)(sm + OFF_HSB);
    float* red = (float*)(sm + OFF_RED);
    __shared__ int is_last;

    const int tid = threadIdx.x;
    const int wid = tid >> 5;
    const int lid = tid & 31;
    const int m0  = blockIdx.x * TM;
    const int n0  = blockIdx.y * TN;

    // ---- Phase 0: fire-and-forget cp.async prefetch of raw B tile ----
    {
        const char* gb = (const char*)(train_x + (size_t)n0 * DDIM);
        uint32_t dbase = smem_u32(sm + OFF_BRAW);
        #pragma unroll
        for (int i = 0; i < 8; i++) {           // 2048 x 16B / 256 thr
            int off = (i * 256 + tid) * 16;
            cp_async16(dbase + off, gb + off);
        }
        asm volatile("cp.async.commit_group;" ::: "memory");
    }

    // ---- Convert A tile fp32->bf16 (raw), exact fp32 half-norms ----
    {
        const float4* t4 = (const float4*)(test_x + (size_t)m0 * DDIM);
        #pragma unroll
        for (int i = 0; i < 8; i++) {
            int idx = i * 256 + tid;
            int row = idx >> 4, j = idx & 15;      // 16 float4 per 64-float row
            float4 v = t4[idx];
            float s = v.x*v.x + v.y*v.y + v.z*v.z + v.w*v.w;
            s += __shfl_xor_sync(~0u, s, 8);
            s += __shfl_xor_sync(~0u, s, 4);
            s += __shfl_xor_sync(~0u, s, 2);
            s += __shfl_xor_sync(~0u, s, 1);
            if ((tid & 15) == 0) hsa[row] = HS * s;
            uint32_t o = sw128((uint32_t)(row * 128 + j * 8));
            *(uint2*)(sm + OFF_A + o) = make_uint2(bf16x2_pack(v.x, v.y),
                                                   bf16x2_pack(v.z, v.w));
        }
    }
    asm volatile("cp.async.wait_group 0;" ::: "memory");   // B raw landed
    __syncthreads();   // A + hsa + Braw visible

    // ---- Warp tiling: warp (mw, nw) owns rows mw*32..+31, cols nw*64..+63 ----
    const int mw = wid & 3;
    const int nw = wid >> 2;
    const uint32_t baseA = smem_u32(sm + OFF_A);
    const uint32_t baseB = smem_u32(sm + OFF_B);

    // A fragments: issue ldsm now so latency overlaps B's convert below
    uint32_t aF[2][4][4];
    {
        int arow = mw * 32 + (lid & 7) + ((lid >> 3) & 1) * 8;
        int acol = (lid >> 4) * 16;
        #pragma unroll
        for (int mt = 0; mt < 2; mt++)
            #pragma unroll
            for (int ks = 0; ks < 4; ks++)
                ldsm4(aF[mt][ks],
                      baseA + sw128((uint32_t)((arow + mt * 16) * 128 + ks * 32 + acol)));
    }
    const int g  = lid >> 2;    // row within 8-group (mma C layout)
    const int tk = lid & 3;     // col-pair
    float hra[2][2];
    #pragma unroll
    for (int mt = 0; mt < 2; mt++) {
        hra[mt][0] = hsa[mw * 32 + mt * 16 + g];
        hra[mt][1] = hsa[mw * 32 + mt * 16 + g + 8];
    }

    // ---- Convert B tile from SMEM (LDS latency, not LDG) ----
    {
        const float4* braw = (const float4*)(sm + OFF_BRAW);
        #pragma unroll
        for (int i = 0; i < 4; i++) {             // 1024 8-float chunks
            int idx = i * 256 + tid;
            int r = idx >> 3, j = idx & 7;
            float4 v0 = braw[idx * 2], v1 = braw[idx * 2 + 1];
            float s = v0.x*v0.x + v0.y*v0.y + v0.z*v0.z + v0.w*v0.w
                    + v1.x*v1.x + v1.y*v1.y + v1.z*v1.z + v1.w*v1.w;
            s += __shfl_xor_sync(~0u, s, 1);
            s += __shfl_xor_sync(~0u, s, 2);
            s += __shfl_xor_sync(~0u, s, 4);
            if (j == 0) hsb[r] = HS * s;
            uint4 pk = make_uint4(bf16x2_pack(v0.x, v0.y), bf16x2_pack(v0.z, v0.w),
                                  bf16x2_pack(v1.x, v1.y), bf16x2_pack(v1.z, v1.w));
            *(uint4*)(sm + OFF_B + sw128((uint32_t)(r * 128 + j * 16))) = pk;
        }
    }
    __syncthreads();   // B + hsb visible

    // per-warp conservative flush threshold (exact: exp2(x)=0 in fp32, x<=-150)
    float thr;
    {
        float va = hsa[mw * 32 + lid];
        float vb = fminf(hsb[nw * 64 + lid], hsb[nw * 64 + 32 + lid]);
        #pragma unroll
        for (int s = 16; s; s >>= 1) {
            va = fminf(va, __shfl_xor_sync(~0u, va, s));
            vb = fminf(vb, __shfl_xor_sync(~0u, vb, s));
        }
        thr = (va + vb - 151.0f) * INVCC;   // d <= thr  =>  all exp2 == 0
    }

    // B ldmatrix.x4 base addresses: lanes 0-15 -> chunk p*2, lanes 16-31 -> p*2+1
    uint32_t bAddr4[4];
    {
        int rowb = nw * 64 + ((lid >> 4) & 1) * 8 + (lid & 7);
        int colb = ((lid >> 3) & 1) * 16;
        #pragma unroll
        for (int ks = 0; ks < 4; ks++)
            bAddr4[ks] = baseB + sw128((uint32_t)(rowb * 128 + ks * 32 + colb));
    }

    float acc[2][2] = {{0.f, 0.f}, {0.f, 0.f}};

    #pragma unroll
    for (int p = 0; p < 4; p++) {                 // 4 pairs of 8-col chunks
        const uint32_t boff = (uint32_t)p * 2048; // +16 rows; swizzle-invariant
        uint32_t bF[4][4];
        #pragma unroll
        for (int ks = 0; ks < 4; ks++)
            ldsm4(bF[ks], bAddr4[ks] + boff);

        float d[2][2][4];                          // [mt][chunk-in-pair][4]
        #pragma unroll
        for (int mt = 0; mt < 2; mt++)
            #pragma unroll
            for (int c = 0; c < 2; c++)
                #pragma unroll
                for (int q = 0; q < 4; q++) d[mt][c][q] = 0.f;

        #pragma unroll
        for (int ks = 0; ks < 4; ks++)
            #pragma unroll
            for (int mt = 0; mt < 2; mt++) {
                mma16816(d[mt][0], aF[mt][ks], bF[ks][0], bF[ks][1]);
                mma16816(d[mt][1], aF[mt][ks], bF[ks][2], bF[ks][3]);
            }

        // pairwise max tree over the 16 raw dot values
        float m01 = fmaxf(fmaxf(d[0][0][0], d[0][0][1]), fmaxf(d[0][0][2], d[0][0][3]));
        float m23 = fmaxf(fmaxf(d[0][1][0], d[0][1][1]), fmaxf(d[0][1][2], d[0][1][3]));
        float m45 = fmaxf(fmaxf(d[1][0][0], d[1][0][1]), fmaxf(d[1][0][2], d[1][0][3]));
        float m67 = fmaxf(fmaxf(d[1][1][0], d[1][1][1]), fmaxf(d[1][1][2], d[1][1][3]));
        float mx  = fmaxf(fmaxf(m01, m23), fmaxf(m45, m67));

        if (mx > thr) {   // rare exact path
            float2 hb0 = *(const float2*)&hsb[nw * 64 + p * 16 + tk * 2];
            float2 hb1 = *(const float2*)&hsb[nw * 64 + p * 16 + 8 + tk * 2];
            #pragma unroll
            for (int mt = 0; mt < 2; mt++)
                #pragma unroll
                for (int c = 0; c < 2; c++) {
                    float hbx = c ? hb1.x : hb0.x;
                    float hby = c ? hb1.y : hb0.y;
                    acc[mt][0] += ex2f(fmaf(d[mt][c][0], CC, -(hra[mt][0] + hbx)))
                                + ex2f(fmaf(d[mt][c][1], CC, -(hra[mt][0] + hby)));
                    acc[mt][1] += ex2f(fmaf(d[mt][c][2], CC, -(hra[mt][1] + hbx)))
                                + ex2f(fmaf(d[mt][c][3], CC, -(hra[mt][1] + hby)));
                }
        }
    }

    // ---- reduce across the 4 col-pair lanes; write per-(nw) row sums ----
    #pragma unroll
    for (int mt = 0; mt < 2; mt++)
        #pragma unroll
        for (int rr = 0; rr < 2; rr++) {
            float v = acc[mt][rr];
            v += __shfl_xor_sync(~0u, v, 1);
            v += __shfl_xor_sync(~0u, v, 2);
            acc[mt][rr] = v;
        }
    if (tk == 0) {
        #pragma unroll
        for (int mt = 0; mt < 2; mt++) {
            red[nw * TM + mw * 32 + mt * 16 + g]     = acc[mt][0];
            red[nw * TM + mw * 32 + mt * 16 + g + 8] = acc[mt][1];
        }
    }
    __syncthreads();

    if (tid < TM)
        g_scratch[blockIdx.y * MTOT + m0 + tid] =
            red[tid] + red[TM + tid];

    // ---- last block per m-tile: deterministic final reduction ----
    if (tid == 0) {
        __threadfence();
        int old = atomicAdd(&g_cnt[blockIdx.x], 1);
        is_last = (old == NSPLIT - 1);
        if (is_last) g_cnt[blockIdx.x] = 0;   // reset for graph replay
    }
    __syncthreads();
    if (is_last) {
        __threadfence();
        if (tid < TM) {
            float s = 0.f;
            #pragma unroll
            for (int j = 0; j < NSPLIT; j++)
                s += g_scratch[j * MTOT + m0 + tid];
            out[m0 + tid] = s * (9.973557010f / 4096.0f);  // rsqrt(2*pi*var)/N
        }
    }
}

extern "C" void kernel_launch(void* const* d_in, const int* in_sizes, int n_in,
                              void* d_out, int out_size)
{
    const float* test_x  = (const float*)d_in[0];   // [1024,64]
    const float* train_x = (const float*)d_in[1];   // [4096,64]
    float* out = (float*)d_out;                     // [1024]

    static int inited = 0;
    if (!inited) {
        cudaFuncSetAttribute(kde_mma,
                             cudaFuncAttributeMaxDynamicSharedMemorySize,
                             SMEM_BYTES);
        inited = 1;
    }
    dim3 grid(MT, NSPLIT);   // (8,32) = 256 CTAs, one wave @ occ 2
    kde_mma<<<grid, 256, SMEM_BYTES>>>(test_x, train_x, out);
}

// round 17
// speedup vs baseline: 1.0208x; 1.0208x over previous
#include <cuda_runtime.h>
#include <cstdint>

// ---------------- problem constants ----------------
#define DDIM    64
#define MTOT    1024
#define NTRAIN  4096
#define TM      128                // CTA M tile
#define TN      128                // CTA N tile
#define NSPLIT  (NTRAIN / TN)      // 32
#define MT      (MTOT / TM)        // 8
#define CC      901.6844f          // log2(e)/var, var = 0.0016
#define HS      450.8422f          // 0.5*CC

// deterministic cross-block scratch + self-resetting counters
__device__ float g_scratch[NSPLIT * MTOT];
__device__ int   g_cnt[MT];

struct SmemT {
    alignas(1024) unsigned char A[TM * 128];   // bf16 [row][64], SW128 swizzled (raw)
    alignas(1024) unsigned char B[TN * 128];   // bf16 [row][64], SW128 swizzled (raw)
    float hsa[TM];     // HS * ||a||^2 (exact fp32)
    float hsb[TN];     // HS * ||b||^2
    float red[2][TM];
};

__device__ __forceinline__ uint32_t smem_u32(const void* p) {
    return (uint32_t)__cvta_generic_to_shared(p);
}
__device__ __forceinline__ uint32_t bf16x2_pack(float lo, float hi) {
    uint32_t r;
    asm("cvt.rn.bf16x2.f32 %0, %1, %2;" : "=r"(r) : "f"(hi), "f"(lo));
    return r;
}
__device__ __forceinline__ float ex2f(float x) {
    float y; asm("ex2.approx.f32 %0, %1;" : "=f"(y) : "f"(x)); return y;
}
__device__ __forceinline__ uint32_t sw128(uint32_t o) {
    return o ^ ((o >> 3) & 0x70);
}
__device__ __forceinline__ void ldsm4(uint32_t r[4], uint32_t addr) {
    asm volatile("ldmatrix.sync.aligned.m8n8.x4.shared.b16 {%0,%1,%2,%3}, [%4];"
                 : "=r"(r[0]), "=r"(r[1]), "=r"(r[2]), "=r"(r[3]) : "r"(addr));
}
__device__ __forceinline__ void mma16816(float d[4], const uint32_t a[4],
                                         uint32_t b0, uint32_t b1) {
    asm volatile("mma.sync.aligned.m16n8k16.row.col.f32.bf16.bf16.f32 "
                 "{%0,%1,%2,%3}, {%4,%5,%6,%7}, {%8,%9}, {%0,%1,%2,%3};"
                 : "+f"(d[0]), "+f"(d[1]), "+f"(d[2]), "+f"(d[3])
                 : "r"(a[0]), "r"(a[1]), "r"(a[2]), "r"(a[3]),
                   "r"(b0), "r"(b1));
}

__global__ __launch_bounds__(256, 2)
void kde_mma(const float* __restrict__ test_x,
             const float* __restrict__ train_x,
             float* __restrict__ out)
{
    __shared__ SmemT smem;
    __shared__ int is_last;

    const int tid = threadIdx.x;
    const int wid = tid >> 5;
    const int lid = tid & 31;
    const int m0  = blockIdx.x * TM;
    const int n0  = blockIdx.y * TN;

    // ---- Convert A tile fp32->bf16 (raw), exact fp32 half-norms ----
    {
        const float4* t4 = (const float4*)(test_x + (size_t)m0 * DDIM);
        #pragma unroll
        for (int i = 0; i < 8; i++) {
            int idx = i * 256 + tid;
            int row = idx >> 4, j = idx & 15;      // 16 float4 per 64-float row
            float4 v = t4[idx];
            float s = v.x*v.x + v.y*v.y + v.z*v.z + v.w*v.w;
            s += __shfl_xor_sync(~0u, s, 8);
            s += __shfl_xor_sync(~0u, s, 4);
            s += __shfl_xor_sync(~0u, s, 2);
            s += __shfl_xor_sync(~0u, s, 1);
            if ((tid & 15) == 0) smem.hsa[row] = HS * s;
            uint32_t o = sw128((uint32_t)(row * 128 + j * 8));
            *(uint2*)(smem.A + o) = make_uint2(bf16x2_pack(v.x, v.y),
                                               bf16x2_pack(v.z, v.w));
        }
    }
    __syncthreads();   // A + hsa visible

    // ---- Warp tiling: warp (mw, nw) owns rows mw*32..+31, cols nw*64..+63 ----
    const int mw = wid & 3;
    const int nw = wid >> 2;
    const uint32_t baseA = smem_u32(smem.A);
    const uint32_t baseB = smem_u32(smem.B);

    // A fragments: issue ldsm now so latency overlaps B's global loads below
    uint32_t aF[2][4][4];
    {
        int arow = mw * 32 + (lid & 7) + ((lid >> 3) & 1) * 8;
        int acol = (lid >> 4) * 16;
        #pragma unroll
        for (int mt = 0; mt < 2; mt++)
            #pragma unroll
            for (int ks = 0; ks < 4; ks++)
                ldsm4(aF[mt][ks],
                      baseA + sw128((uint32_t)((arow + mt * 16) * 128 + ks * 32 + acol)));
    }
    const int g  = lid >> 2;    // row within 8-group (mma C layout)
    const int tk = lid & 3;     // col-pair
    float hra[2][2];
    #pragma unroll
    for (int mt = 0; mt < 2; mt++) {
        hra[mt][0] = smem.hsa[mw * 32 + mt * 16 + g];
        hra[mt][1] = smem.hsa[mw * 32 + mt * 16 + g + 8];
    }

    // ---- Convert B tile (raw bf16) ----
    {
        const float4* t4 = (const float4*)(train_x + (size_t)n0 * DDIM);
        #pragma unroll
        for (int i = 0; i < 8; i++) {
            int idx = i * 256 + tid;
            int row = idx >> 4, j = idx & 15;
            float4 v = t4[idx];
            float s = v.x*v.x + v.y*v.y + v.z*v.z + v.w*v.w;
            s += __shfl_xor_sync(~0u, s, 8);
            s += __shfl_xor_sync(~0u, s, 4);
            s += __shfl_xor_sync(~0u, s, 2);
            s += __shfl_xor_sync(~0u, s, 1);
            if ((tid & 15) == 0) smem.hsb[row] = HS * s;
            uint32_t o = sw128((uint32_t)(row * 128 + j * 8));
            *(uint2*)(smem.B + o) = make_uint2(bf16x2_pack(v.x, v.y),
                                               bf16x2_pack(v.z, v.w));
        }
    }
    __syncthreads();   // B + hsb visible

    // B ldmatrix.x4 base addresses: lanes 0-15 -> chunk p*2, lanes 16-31 -> p*2+1
    uint32_t bAddr4[4];
    {
        int rowb = nw * 64 + ((lid >> 4) & 1) * 8 + (lid & 7);
        int colb = ((lid >> 3) & 1) * 16;
        #pragma unroll
        for (int ks = 0; ks < 4; ks++)
            bAddr4[ks] = baseB + sw128((uint32_t)(rowb * 128 + ks * 32 + colb));
    }

    float acc[2][2] = {{0.f, 0.f}, {0.f, 0.f}};

    #pragma unroll
    for (int p = 0; p < 4; p++) {                 // 4 pairs of 8-col chunks
        const uint32_t boff = (uint32_t)p * 2048; // +16 rows; swizzle-invariant
        uint32_t bF[4][4];
        #pragma unroll
        for (int ks = 0; ks < 4; ks++)
            ldsm4(bF[ks], bAddr4[ks] + boff);

        float d[2][2][4];                          // [mt][chunk-in-pair][4]
        #pragma unroll
        for (int mt = 0; mt < 2; mt++)
            #pragma unroll
            for (int c = 0; c < 2; c++)
                #pragma unroll
                for (int q = 0; q < 4; q++) d[mt][c][q] = 0.f;

        #pragma unroll
        for (int ks = 0; ks < 4; ks++) {
            #pragma unroll
            for (int mt = 0; mt < 2; mt++) {
                mma16816(d[mt][0], aF[mt][ks], bF[ks][0], bF[ks][1]);
                mma16816(d[mt][1], aF[mt][ks], bF[ks][2], bF[ks][3]);
            }
        }

        // Epilogue: t = CC*d - (hra + hb); pair-wide flush-to-zero guard
        float2 hb0 = *(const float2*)&smem.hsb[nw * 64 + p * 16 + tk * 2];
        float2 hb1 = *(const float2*)&smem.hsb[nw * 64 + p * 16 + 8 + tk * 2];

        float t[2][2][4];
        float mx = -1e30f;
        #pragma unroll
        for (int mt = 0; mt < 2; mt++) {
            #pragma unroll
            for (int c = 0; c < 2; c++) {
                float hbx = c ? hb1.x : hb0.x;
                float hby = c ? hb1.y : hb0.y;
                t[mt][c][0] = fmaf(d[mt][c][0], CC, -(hra[mt][0] + hbx));
                t[mt][c][1] = fmaf(d[mt][c][1], CC, -(hra[mt][0] + hby));
                t[mt][c][2] = fmaf(d[mt][c][2], CC, -(hra[mt][1] + hbx));
                t[mt][c][3] = fmaf(d[mt][c][3], CC, -(hra[mt][1] + hby));
                #pragma unroll
                for (int q = 0; q < 4; q++) mx = fmaxf(mx, t[mt][c][q]);
            }
        }
        if (mx > -150.f) {   // exact: exp2(x) == 0 in fp32 for x <= -150
            #pragma unroll
            for (int mt = 0; mt < 2; mt++)
                #pragma unroll
                for (int c = 0; c < 2; c++) {
                    acc[mt][0] += ex2f(t[mt][c][0]) + ex2f(t[mt][c][1]);
                    acc[mt][1] += ex2f(t[mt][c][2]) + ex2f(t[mt][c][3]);
                }
        }
    }

    // ---- reduce across the 4 col-pair lanes; write per-(nw) row sums ----
    #pragma unroll
    for (int mt = 0; mt < 2; mt++)
        #pragma unroll
        for (int rr = 0; rr < 2; rr++) {
            float v = acc[mt][rr];
            v += __shfl_xor_sync(~0u, v, 1);
            v += __shfl_xor_sync(~0u, v, 2);
            acc[mt][rr] = v;
        }
    if (tk == 0) {
        #pragma unroll
        for (int mt = 0; mt < 2; mt++) {
            smem.red[nw][mw * 32 + mt * 16 + g]     = acc[mt][0];
            smem.red[nw][mw * 32 + mt * 16 + g + 8] = acc[mt][1];
        }
    }
    __syncthreads();

    if (tid < TM)
        g_scratch[blockIdx.y * MTOT + m0 + tid] =
            smem.red[0][tid] + smem.red[1][tid];

    // ---- last block per m-tile: deterministic final reduction ----
    if (tid == 0) {
        __threadfence();
        int old = atomicAdd(&g_cnt[blockIdx.x], 1);
        is_last = (old == NSPLIT - 1);
        if (is_last) g_cnt[blockIdx.x] = 0;   // reset for graph replay
    }
    __syncthreads();
    if (is_last) {
        __threadfence();
        if (tid < TM) {
            float s = 0.f;
            #pragma unroll
            for (int j = 0; j < NSPLIT; j++)
                s += g_scratch[j * MTOT + m0 + tid];
            out[m0 + tid] = s * (9.973557010f / 4096.0f);  // rsqrt(2*pi*var)/N
        }
    }
}

extern "C" void kernel_launch(void* const* d_in, const int* in_sizes, int n_in,
                              void* d_out, int out_size)
{
    const float* test_x  = (const float*)d_in[0];   // [1024,64]
    const float* train_x = (const float*)d_in[1];   // [4096,64]
    float* out = (float*)d_out;                     // [1024]

    dim3 grid(MT, NSPLIT);   // (8,32) = 256 CTAs, one wave @ occ 2
    kde_mma<<<grid, 256>>>(test_x, train_x, out);
}